// round 10
// baseline (speedup 1.0000x reference)
#include <cuda_runtime.h>

#define H 512
#define W 512
#define NIMG 48
#define TC 256                 // tile cols per block (== blockDim.x)
#define TR 16                  // tile rows per block
#define SW 260                 // smem row stride (258 used + pad)
#define BLOCK 256

__device__ __forceinline__ float med3f(float a, float b, float c) {
    return fmaxf(fminf(a, b), fminf(fmaxf(a, b), c));
}

__global__ __launch_bounds__(BLOCK)
void MedianFilter_22737556865485_kernel(const float* __restrict__ in,
                                        float* __restrict__ out) {
    __shared__ float sm[TR + 2][SW];

    const int tid = threadIdx.x;
    const int c0  = blockIdx.x * TC;
    const int r0  = blockIdx.y * TR;
    const int img = blockIdx.z;

    const float* base  = in  + (size_t)img * (H * W);
    float*       obase = out + (size_t)img * (H * W);

    // ---- Cooperative fill: rows r0-1 .. r0+TR, cols c0-1 .. c0+TC ----
    // Column reflect is loop-invariant per thread.
    int gc = c0 - 1 + tid;                      // smem col 'tid'
    gc = (gc < 0) ? 1 : gc;                     // reflect col -1 -> 1 (max gc = c0+254 < W)
    int gc2 = c0 - 1 + TC + tid;                // smem cols 256,257 (tid < 2 only)
    if (gc2 >= W) gc2 = W - 2;                  // reflect col W -> W-2

#pragma unroll
    for (int r = 0; r < TR + 2; ++r) {
        int gr = r0 - 1 + r;
        gr = (gr < 0) ? 1 : ((gr >= H) ? (H - 2) : gr);   // reflect rows
        const float* grow = base + (size_t)gr * W;
        sm[r][tid] = grow[gc];                  // coalesced: lanes hit consecutive cols
        if (tid < 2) sm[r][TC + tid] = grow[gc2];
    }
    __syncthreads();

    // ---- Compute: each thread owns one output column, walks TR rows ----
    // Row-triple (min3, med3, max3 over 3 horizontal neighbors) kept in a
    // 3-deep rotating history; each triple serves 3 vertically-adjacent outputs.
    const int sc = tid + 1;                     // this thread's smem center col
    float lo[3], mi[3], hi[3];

#pragma unroll
    for (int r = 0; r < 2; ++r) {               // prime history with smem rows 0,1
        const float a = sm[r][sc - 1], b = sm[r][sc], c = sm[r][sc + 1];
        lo[r] = fminf(fminf(a, b), c);
        hi[r] = fmaxf(fmaxf(a, b), c);
        mi[r] = med3f(a, b, c);
    }

    float* po = obase + (size_t)r0 * W + c0 + tid;
#pragma unroll
    for (int i = 0; i < TR; ++i) {
        const int k = (i + 2) % 3;              // compile-time rotation (full unroll)
        const float a = sm[i + 2][sc - 1], b = sm[i + 2][sc], c = sm[i + 2][sc + 1];
        lo[k] = fminf(fminf(a, b), c);          // min of row triple
        hi[k] = fmaxf(fmaxf(a, b), c);          // max of row triple
        mi[k] = med3f(a, b, c);                 // med of row triple

        const float A = fmaxf(fmaxf(lo[0], lo[1]), lo[2]);  // max of mins
        const float C = fminf(fminf(hi[0], hi[1]), hi[2]);  // min of maxes
        const float B = med3f(mi[0], mi[1], mi[2]);         // med of meds
        *po = med3f(A, B, C);                               // exact median9
        po += W;                                // warp-coalesced 128B store per row
    }
}

extern "C" void kernel_launch(void* const* d_in, const int* in_sizes, int n_in,
                              void* d_out, int out_size) {
    const float* in  = (const float*)d_in[0];
    float*       out = (float*)d_out;
    dim3 grid(W / TC, H / TR, NIMG);            // (2, 32, 48) = 3072 blocks
    MedianFilter_22737556865485_kernel<<<grid, BLOCK>>>(in, out);
}